// round 1
// baseline (speedup 1.0000x reference)
#include <cuda_runtime.h>
#include <cuda_bf16.h>

// CrossNet: xi_{l+1} = x0 * dot(xi_l, W[l]) + B[l] + xi_l, for l = 0..2
// x0: [BATCH, DIM] f32, W: [ORDER, DIM] f32, B: [ORDER, DIM] f32, out: [BATCH, DIM] f32
// Warp-per-row, register-resident state, warp-shuffle reductions.

#define DIMV (1024 / 4)   // float4s per row = 256
#define PASSES 8          // 256 float4s / 32 lanes

__global__ __launch_bounds__(256) void crossnet_kernel(
    const float4* __restrict__ x0,
    const float4* __restrict__ W,
    const float4* __restrict__ B,
    float4* __restrict__ out,
    int batch)
{
    const int warp_global = (blockIdx.x * blockDim.x + threadIdx.x) >> 5;
    const int lane = threadIdx.x & 31;
    if (warp_global >= batch) return;

    const float4* xrow = x0 + (size_t)warp_global * DIMV;

    float4 x[PASSES];   // anchor x0 (constant across layers)
    float4 xi[PASSES];  // evolving state

#pragma unroll
    for (int p = 0; p < PASSES; ++p) {
        x[p] = xrow[p * 32 + lane];
        xi[p] = x[p];
    }

#pragma unroll
    for (int l = 0; l < 3; ++l) {
        const float4* wrow = W + l * DIMV;
        const float4* brow = B + l * DIMV;

        // Partial dot(xi, W[l]) over this lane's 8 float4s
        float s = 0.0f;
#pragma unroll
        for (int p = 0; p < PASSES; ++p) {
            float4 wv = wrow[p * 32 + lane];
            s = fmaf(xi[p].x, wv.x, s);
            s = fmaf(xi[p].y, wv.y, s);
            s = fmaf(xi[p].z, wv.z, s);
            s = fmaf(xi[p].w, wv.w, s);
        }
        // Warp tree reduction
#pragma unroll
        for (int o = 16; o > 0; o >>= 1)
            s += __shfl_xor_sync(0xffffffffu, s, o);

        // xi += x0 * s + B[l]
#pragma unroll
        for (int p = 0; p < PASSES; ++p) {
            float4 bv = brow[p * 32 + lane];
            xi[p].x = fmaf(x[p].x, s, xi[p].x + bv.x);
            xi[p].y = fmaf(x[p].y, s, xi[p].y + bv.y);
            xi[p].z = fmaf(x[p].z, s, xi[p].z + bv.z);
            xi[p].w = fmaf(x[p].w, s, xi[p].w + bv.w);
        }
    }

    float4* orow = out + (size_t)warp_global * DIMV;
#pragma unroll
    for (int p = 0; p < PASSES; ++p)
        orow[p * 32 + lane] = xi[p];
}

extern "C" void kernel_launch(void* const* d_in, const int* in_sizes, int n_in,
                              void* d_out, int out_size)
{
    const float4* x0 = (const float4*)d_in[0];
    const float4* W  = (const float4*)d_in[1];
    const float4* B  = (const float4*)d_in[2];
    float4* out = (float4*)d_out;

    const int batch = in_sizes[0] / 1024;   // rows
    const int threads = 256;                // 8 warps -> 8 rows per block
    const int blocks = (batch * 32 + threads - 1) / threads;

    crossnet_kernel<<<blocks, threads>>>(x0, W, B, out, batch);
}